// round 13
// baseline (speedup 1.0000x reference)
#include <cuda_runtime.h>
#include <cuda_bf16.h>
#include <math.h>
#include <stdint.h>

// Problem constants
#define BSZ   2
#define SEQ   1024
#define DMODEL 4096
#define NH    32
#define NKVH  8
#define HD    128
#define MROWS (BSZ * SEQ)      // 2048
#define QCOLS (NH * HD)        // 4096
#define KCOLS (NKVH * HD)      // 1024

// Scratch (no allocations allowed — device globals)
__device__ float g_Q [(size_t)MROWS * QCOLS];
__device__ float g_K [(size_t)MROWS * KCOLS];
__device__ float g_V [(size_t)MROWS * KCOLS];
__device__ float g_AO[(size_t)MROWS * QCOLS];

// ---------------------------------------------------------------------------
// fp32 SGEMM:  C[M,N] = A[M,K] @ W[K,N] (+ bias[N])
// BM=BN=128, BK=16, 256 threads, 8x8 microtile.
// Double-buffered smem, register-staged GMEM prefetch, ONE sync per iter.
// Plain scalar FFMA. M,N % 128 == 0, K % 16 == 0 (true for all calls).
// ---------------------------------------------------------------------------
__global__ __launch_bounds__(256, 2)
void sgemm_ffma(const float* __restrict__ A, const float* __restrict__ W,
                const float* __restrict__ bias, float* __restrict__ C,
                int M, int N, int K)
{
    __shared__ __align__(16) float As[2][16][128];   // [buf][k][m] (transposed)
    __shared__ __align__(16) float Bs[2][16][128];   // [buf][k][n]

    const int t   = threadIdx.x;
    const int tx  = t & 15;            // 16 col groups
    const int ty  = t >> 4;            // 16 row groups
    const int row0 = blockIdx.y * 128;
    const int col0 = blockIdx.x * 128;

    float acc[8][8];
#pragma unroll
    for (int i = 0; i < 8; i++)
#pragma unroll
        for (int j = 0; j < 8; j++) acc[i][j] = 0.f;

    // staging mapping: each thread one float4 of A (x2 rows), one of B (x2 k)
    const int a_r  = t >> 2, a_k4 = t & 3;
    const int b_kk = t >> 5, b_n4 = t & 31;
    float4 pa[2], pb[2];

    auto LOAD = [&](int kb) {
        pa[0] = *reinterpret_cast<const float4*>(A + (size_t)(row0 + a_r) * K + kb + a_k4 * 4);
        pa[1] = *reinterpret_cast<const float4*>(A + (size_t)(row0 + 64 + a_r) * K + kb + a_k4 * 4);
        pb[0] = *reinterpret_cast<const float4*>(W + (size_t)(kb + b_kk) * N + col0 + b_n4 * 4);
        pb[1] = *reinterpret_cast<const float4*>(W + (size_t)(kb + 8 + b_kk) * N + col0 + b_n4 * 4);
    };
    auto STORE = [&](int buf) {
        As[buf][a_k4 * 4 + 0][a_r] = pa[0].x;
        As[buf][a_k4 * 4 + 1][a_r] = pa[0].y;
        As[buf][a_k4 * 4 + 2][a_r] = pa[0].z;
        As[buf][a_k4 * 4 + 3][a_r] = pa[0].w;
        As[buf][a_k4 * 4 + 0][64 + a_r] = pa[1].x;
        As[buf][a_k4 * 4 + 1][64 + a_r] = pa[1].y;
        As[buf][a_k4 * 4 + 2][64 + a_r] = pa[1].z;
        As[buf][a_k4 * 4 + 3][64 + a_r] = pa[1].w;
        *reinterpret_cast<float4*>(&Bs[buf][b_kk][b_n4 * 4])     = pb[0];
        *reinterpret_cast<float4*>(&Bs[buf][b_kk + 8][b_n4 * 4]) = pb[1];
    };

    LOAD(0);
    STORE(0);
    __syncthreads();

    const int niter = K >> 4;
    for (int it = 0; it < niter; it++) {
        const int cur = it & 1;
        if (it + 1 < niter) LOAD((it + 1) << 4);   // prefetch next tile to regs

#pragma unroll
        for (int kk = 0; kk < 16; kk++) {
            float ra[8], rb[8];
            *reinterpret_cast<float4*>(&ra[0]) =
                *reinterpret_cast<const float4*>(&As[cur][kk][ty * 4]);
            *reinterpret_cast<float4*>(&ra[4]) =
                *reinterpret_cast<const float4*>(&As[cur][kk][64 + ty * 4]);
            *reinterpret_cast<float4*>(&rb[0]) =
                *reinterpret_cast<const float4*>(&Bs[cur][kk][tx * 4]);
            *reinterpret_cast<float4*>(&rb[4]) =
                *reinterpret_cast<const float4*>(&Bs[cur][kk][64 + tx * 4]);
#pragma unroll
            for (int i = 0; i < 8; i++)
#pragma unroll
                for (int j = 0; j < 8; j++)
                    acc[i][j] += ra[i] * rb[j];
        }

        if (it + 1 < niter) {
            STORE(cur ^ 1);
            __syncthreads();
        }
    }

    // Epilogue
#pragma unroll
    for (int i = 0; i < 8; i++) {
        int r = row0 + ((i < 4) ? (ty * 4 + i) : (64 + ty * 4 + (i - 4)));
#pragma unroll
        for (int jh = 0; jh < 2; jh++) {
            int cb = col0 + (jh ? (64 + tx * 4) : (tx * 4));
            float4 v = make_float4(acc[i][jh * 4 + 0], acc[i][jh * 4 + 1],
                                   acc[i][jh * 4 + 2], acc[i][jh * 4 + 3]);
            if (bias) {
                v.x += bias[cb + 0]; v.y += bias[cb + 1];
                v.z += bias[cb + 2]; v.w += bias[cb + 3];
            }
            *reinterpret_cast<float4*>(C + (size_t)r * N + cb) = v;
        }
    }
}

// ---------------------------------------------------------------------------
// RoPE (in-place): buf layout [MROWS][nheads*128].
// ---------------------------------------------------------------------------
__global__ void rope_kernel(float* __restrict__ buf,
                            const int* __restrict__ sidx, int nheads)
{
    int idx = blockIdx.x * blockDim.x + threadIdx.x;
    int total = MROWS * nheads * 64;
    if (idx >= total) return;
    int d   = idx & 63;
    int rem = idx >> 6;
    int h   = rem % nheads;
    int row = rem / nheads;
    int s   = row & (SEQ - 1);

    double pos = (double)sidx[s];
    double ang = pos * exp(-((double)d / 64.0) * 13.815510557964274);
    double sn, cs;
    sincos(ang, &sn, &cs);

    float* p = buf + (size_t)row * (nheads * 128) + h * 128 + d;
    float t1 = p[0];
    float t2 = p[64];
    p[0]  = t1 * (float)cs - t2 * (float)sn;
    p[64] = t2 * (float)cs + t1 * (float)sn;
}

// ---------------------------------------------------------------------------
// Flash attention (fp32, causal). BQ=64, BK=32, 256 threads.
// ---------------------------------------------------------------------------
__global__ __launch_bounds__(256)
void attn_kernel(const float* __restrict__ Q, const float* __restrict__ Kc,
                 const float* __restrict__ Vc, const int* __restrict__ sidx,
                 float* __restrict__ O)
{
    __shared__ float4 Ks[32][32];
    __shared__ float4 Vs[32][32];
    __shared__ int    spos[32];

    const int t   = threadIdx.x;
    const int r   = t >> 2;
    const int sub = t & 3;
    const int b   = blockIdx.z;
    const int h   = blockIdx.y;
    const int q0  = blockIdx.x * 64;
    const int kvh = h >> 2;
    const int sq  = q0 + r;
    const int pos_q = sidx[sq];
    const float scale = 0.08838834764831845f;

    float4 qreg[8];
    {
        const float4* qp = reinterpret_cast<const float4*>(
            Q + (size_t)(b * SEQ + sq) * QCOLS + h * 128 + sub * 32);
#pragma unroll
        for (int c = 0; c < 8; c++) qreg[c] = qp[c];
    }

    float  m = -1e30f, l = 0.f;
    float4 acc[8];
#pragma unroll
    for (int c = 0; c < 8; c++) acc[c] = make_float4(0.f, 0.f, 0.f, 0.f);

    const float* Kbase = Kc + (size_t)b * SEQ * KCOLS + kvh * 128;
    const float* Vbase = Vc + (size_t)b * SEQ * KCOLS + kvh * 128;

    for (int k0 = 0; k0 < q0 + 64; k0 += 32) {
        __syncthreads();
#pragma unroll
        for (int ww = 0; ww < 4; ww++) {
            int f  = ww * 256 + t;
            int j  = f >> 5;
            int i4 = f & 31;
            Ks[j][i4] = *reinterpret_cast<const float4*>(
                Kbase + (size_t)(k0 + j) * KCOLS + i4 * 4);
            Vs[j][i4] = *reinterpret_cast<const float4*>(
                Vbase + (size_t)(k0 + j) * KCOLS + i4 * 4);
        }
        if (t < 32) spos[t] = sidx[k0 + t];
        __syncthreads();

        float sc[32];
        float tmax = -1e30f;
#pragma unroll
        for (int j = 0; j < 32; j++) {
            float s = 0.f;
#pragma unroll
            for (int c0 = 0; c0 < 8; c0++) {
                int c = (c0 + 2 * sub) & 7;
                float4 k4 = Ks[j][sub * 8 + c];
                float4 q4 = qreg[c];
                s += q4.x * k4.x + q4.y * k4.y + q4.z * k4.z + q4.w * k4.w;
            }
            s += __shfl_xor_sync(0xffffffffu, s, 1);
            s += __shfl_xor_sync(0xffffffffu, s, 2);
            s *= scale;
            if (spos[j] > pos_q) s = -1e30f;
            sc[j] = s;
            tmax = fmaxf(tmax, s);
        }

        float m_new = fmaxf(m, tmax);
        float corr  = __expf(m - m_new);
        l *= corr;
#pragma unroll
        for (int c = 0; c < 8; c++) {
            acc[c].x *= corr; acc[c].y *= corr;
            acc[c].z *= corr; acc[c].w *= corr;
        }
#pragma unroll
        for (int j = 0; j < 32; j++) {
            float p = __expf(sc[j] - m_new);
            l += p;
#pragma unroll
            for (int c0 = 0; c0 < 8; c0++) {
                int c = (c0 + 2 * sub) & 7;
                float4 v4 = Vs[j][sub * 8 + c];
                acc[c].x += p * v4.x; acc[c].y += p * v4.y;
                acc[c].z += p * v4.z; acc[c].w += p * v4.w;
            }
        }
        m = m_new;
    }

    float inv = 1.0f / l;
    float4* op = reinterpret_cast<float4*>(
        O + (size_t)(b * SEQ + sq) * QCOLS + h * 128 + sub * 32);
#pragma unroll
    for (int c = 0; c < 8; c++) {
        float4 v = acc[c];
        v.x *= inv; v.y *= inv; v.z *= inv; v.w *= inv;
        op[c] = v;
    }
}

// ---------------------------------------------------------------------------
// Launch: QKV proj -> RoPE -> flash attention -> output proj
// ---------------------------------------------------------------------------
extern "C" void kernel_launch(void* const* d_in, const int* in_sizes, int n_in,
                              void* d_out, int out_size)
{
    (void)in_sizes; (void)n_in; (void)out_size;
    const float* x    = (const float*)d_in[0];
    const int*   sidx = (const int*)  d_in[1];
    const float* Wq = (const float*)d_in[4];
    const float* bq = (const float*)d_in[5];
    const float* Wk = (const float*)d_in[6];
    const float* bk = (const float*)d_in[7];
    const float* Wv = (const float*)d_in[8];
    const float* bv = (const float*)d_in[9];
    const float* Wo = (const float*)d_in[10];
    float* out = (float*)d_out;

    float *pQ, *pK, *pV, *pAO;
    cudaGetSymbolAddress((void**)&pQ,  g_Q);
    cudaGetSymbolAddress((void**)&pK,  g_K);
    cudaGetSymbolAddress((void**)&pV,  g_V);
    cudaGetSymbolAddress((void**)&pAO, g_AO);

    // QKV projections (+bias)
    sgemm_ffma<<<dim3(QCOLS / 128, MROWS / 128), 256>>>(x, Wq, bq, pQ, MROWS, QCOLS, DMODEL);
    sgemm_ffma<<<dim3(KCOLS / 128, MROWS / 128), 256>>>(x, Wk, bk, pK, MROWS, KCOLS, DMODEL);
    sgemm_ffma<<<dim3(KCOLS / 128, MROWS / 128), 256>>>(x, Wv, bv, pV, MROWS, KCOLS, DMODEL);

    // RoPE on Q and K
    rope_kernel<<<(MROWS * NH   * 64 + 255) / 256, 256>>>(pQ, sidx, NH);
    rope_kernel<<<(MROWS * NKVH * 64 + 255) / 256, 256>>>(pK, sidx, NKVH);

    // Causal GQA flash attention
    attn_kernel<<<dim3(SEQ / 64, NH, BSZ), 256>>>(pQ, pK, pV, sidx, pAO);

    // Output projection
    sgemm_ffma<<<dim3(DMODEL / 128, MROWS / 128), 256>>>(pAO, Wo, nullptr, out, MROWS, DMODEL, QCOLS);
}

// round 14
// speedup vs baseline: 1.2516x; 1.2516x over previous
#include <cuda_runtime.h>
#include <cuda_fp16.h>
#include <math.h>
#include <stdint.h>

// Problem constants
#define BSZ   2
#define SEQ   1024
#define DMODEL 4096
#define NH    32
#define NKVH  8
#define HD    128
#define MROWS (BSZ * SEQ)      // 2048
#define QCOLS (NH * HD)        // 4096
#define KCOLS (NKVH * HD)      // 1024

// Scratch (no allocations allowed — device globals)
__device__ float g_Q [(size_t)MROWS * QCOLS];
__device__ float g_K [(size_t)MROWS * KCOLS];
__device__ float g_V [(size_t)MROWS * KCOLS];
__device__ float g_AO[(size_t)MROWS * QCOLS];

// ---------------------------------------------------------------------------
// helpers
// ---------------------------------------------------------------------------
__device__ __forceinline__ uint32_t sptr(const void* p) {
    return (uint32_t)__cvta_generic_to_shared(p);
}
__device__ __forceinline__ void ldm4(uint32_t r[4], uint32_t addr) {
    asm volatile("ldmatrix.sync.aligned.m8n8.x4.shared.b16 {%0,%1,%2,%3}, [%4];"
                 : "=r"(r[0]), "=r"(r[1]), "=r"(r[2]), "=r"(r[3]) : "r"(addr));
}
__device__ __forceinline__ void ldm4t(uint32_t r[4], uint32_t addr) {
    asm volatile("ldmatrix.sync.aligned.m8n8.x4.trans.shared.b16 {%0,%1,%2,%3}, [%4];"
                 : "=r"(r[0]), "=r"(r[1]), "=r"(r[2]), "=r"(r[3]) : "r"(addr));
}
// fp16 mma: D(f32) += A(f16) * B(f16)
__device__ __forceinline__ void mma16816h(float c[4], const uint32_t a[4],
                                          uint32_t b0, uint32_t b1) {
    asm volatile("mma.sync.aligned.m16n8k16.row.col.f32.f16.f16.f32 "
                 "{%0,%1,%2,%3}, {%4,%5,%6,%7}, {%8,%9}, {%0,%1,%2,%3};"
                 : "+f"(c[0]), "+f"(c[1]), "+f"(c[2]), "+f"(c[3])
                 : "r"(a[0]), "r"(a[1]), "r"(a[2]), "r"(a[3]), "r"(b0), "r"(b1));
}

// fp32 pair -> packed f16x2 hi (RN) + lo (RN of residual). Low 16 bits = 'a'.
__device__ __forceinline__ void split2h(float a, float b, uint32_t& hi, uint32_t& lo) {
    __half2 h = __floats2half2_rn(a, b);
    hi = *reinterpret_cast<uint32_t*>(&h);
    float ha = __half2float(__low2half(h));
    float hb = __half2float(__high2half(h));
    __half2 l = __floats2half2_rn(a - ha, b - hb);
    lo = *reinterpret_cast<uint32_t*>(&l);
}
// fp32 pair -> packed f16x2 (RN), no residual. Low 16 bits = 'a'.
__device__ __forceinline__ uint32_t cvt2h(float a, float b) {
    __half2 h = __floats2half2_rn(a, b);
    return *reinterpret_cast<uint32_t*>(&h);
}

// ---------------------------------------------------------------------------
// fp16 2-term split tensor-core GEMM:
//   C[M,N] = A[M,K] @ W[K,N] (+ bias[N]),  fp32 in/out.
//   A = Ah + Al (fp16 pair, near-exact); W quantized to fp16 (Bh only).
//   C ≈ Ah@Bh + Al@Bh   (dropped A@Bl ~ 2^-11 relative)
// CTA tile 128x128x32, 256 threads, 8 warps (2x4) of 64x32 warp tiles.
// Structure identical to the proven round-2 kernel minus the third term.
// ---------------------------------------------------------------------------
__global__ __launch_bounds__(256)
void gemm_f16s(const float* __restrict__ A, const float* __restrict__ W,
               const float* __restrict__ bias, float* __restrict__ C,
               int M, int N, int K)
{
    __shared__ __align__(16) unsigned short Ah[128][40];   // padded: conflict-free
    __shared__ __align__(16) unsigned short Al[128][40];
    __shared__ __align__(16) unsigned short Bh[32][136];

    const int t    = threadIdx.x;
    const int lane = t & 31;
    const int wid  = t >> 5;
    const int wm   = (wid & 1) * 64;    // warp row offset in CTA tile
    const int wn   = (wid >> 1) * 32;   // warp col offset
    const int row0 = blockIdx.y * 128;
    const int col0 = blockIdx.x * 128;

    float c[4][4][4];
#pragma unroll
    for (int i = 0; i < 4; i++)
#pragma unroll
        for (int j = 0; j < 4; j++)
#pragma unroll
            for (int e = 0; e < 4; e++) c[i][j][e] = 0.f;

    float4 pa[4], pb[4];

    auto LOAD = [&](int kb) {
#pragma unroll
        for (int q = 0; q < 4; q++) {
            int fa = t + q * 256;                    // 0..1023
            pa[q] = *reinterpret_cast<const float4*>(
                A + (size_t)(row0 + (fa >> 3)) * K + kb + (fa & 7) * 4);
            pb[q] = *reinterpret_cast<const float4*>(
                W + (size_t)(kb + (fa >> 5)) * N + col0 + (fa & 31) * 4);
        }
    };
    auto STORE = [&]() {
#pragma unroll
        for (int q = 0; q < 4; q++) {
            int fa = t + q * 256;
            {   // A tile -> Ah/Al (2-term split)
                int r = fa >> 3, ca = (fa & 7) * 4;
                uint32_t h0, l0, h1, l1;
                split2h(pa[q].x, pa[q].y, h0, l0);
                split2h(pa[q].z, pa[q].w, h1, l1);
                *reinterpret_cast<uint32_t*>(&Ah[r][ca])     = h0;
                *reinterpret_cast<uint32_t*>(&Ah[r][ca + 2]) = h1;
                *reinterpret_cast<uint32_t*>(&Al[r][ca])     = l0;
                *reinterpret_cast<uint32_t*>(&Al[r][ca + 2]) = l1;
            }
            {   // B tile -> Bh only (fp16 quantized)
                int kk = fa >> 5, cb = (fa & 31) * 4;
                *reinterpret_cast<uint32_t*>(&Bh[kk][cb])     = cvt2h(pb[q].x, pb[q].y);
                *reinterpret_cast<uint32_t*>(&Bh[kk][cb + 2]) = cvt2h(pb[q].z, pb[q].w);
            }
        }
    };

    LOAD(0);
    STORE();
    __syncthreads();

    const int niter = K >> 5;
    for (int it = 0; it < niter; it++) {
        if (it + 1 < niter) LOAD((it + 1) << 5);

#pragma unroll
        for (int ks = 0; ks < 2; ks++) {
            const int k0 = ks << 4;
            const int lr = lane & 15;
            const int lc = (lane >> 4) << 3;

            uint32_t ah[4][4], al4[4][4], bh[4][2];
#pragma unroll
            for (int mi = 0; mi < 4; mi++) {
                ldm4(ah[mi],  sptr(&Ah[wm + mi * 16 + lr][k0 + lc]));
                ldm4(al4[mi], sptr(&Al[wm + mi * 16 + lr][k0 + lc]));
            }
#pragma unroll
            for (int nh = 0; nh < 2; nh++) {
                uint32_t r4[4];
                ldm4t(r4, sptr(&Bh[k0 + lr][wn + nh * 16 + lc]));
                bh[nh * 2][0] = r4[0]; bh[nh * 2][1] = r4[1];
                bh[nh * 2 + 1][0] = r4[2]; bh[nh * 2 + 1][1] = r4[3];
            }
#pragma unroll
            for (int mi = 0; mi < 4; mi++)
#pragma unroll
                for (int ni = 0; ni < 4; ni++) {
                    mma16816h(c[mi][ni], ah[mi],  bh[ni][0], bh[ni][1]);
                    mma16816h(c[mi][ni], al4[mi], bh[ni][0], bh[ni][1]);
                }
        }
        __syncthreads();
        if (it + 1 < niter) {
            STORE();
            __syncthreads();
        }
    }

    // Epilogue: fragment layout m16n8 -> rows lane/4 (+8), cols (lane%4)*2
#pragma unroll
    for (int mi = 0; mi < 4; mi++)
#pragma unroll
        for (int ni = 0; ni < 4; ni++) {
            int r   = row0 + wm + mi * 16 + (lane >> 2);
            int col = col0 + wn + ni * 8 + (lane & 3) * 2;
            float bx = bias ? bias[col]     : 0.f;
            float by = bias ? bias[col + 1] : 0.f;
            float2 v0 = make_float2(c[mi][ni][0] + bx, c[mi][ni][1] + by);
            float2 v1 = make_float2(c[mi][ni][2] + bx, c[mi][ni][3] + by);
            *reinterpret_cast<float2*>(C + (size_t)r * N + col)       = v0;
            *reinterpret_cast<float2*>(C + (size_t)(r + 8) * N + col) = v1;
        }
}

// ---------------------------------------------------------------------------
// RoPE (in-place): buf layout [MROWS][nheads*128].
// ---------------------------------------------------------------------------
__global__ void rope_kernel(float* __restrict__ buf,
                            const int* __restrict__ sidx, int nheads)
{
    int idx = blockIdx.x * blockDim.x + threadIdx.x;
    int total = MROWS * nheads * 64;
    if (idx >= total) return;
    int d   = idx & 63;
    int rem = idx >> 6;
    int h   = rem % nheads;
    int row = rem / nheads;
    int s   = row & (SEQ - 1);

    double pos = (double)sidx[s];
    double ang = pos * exp(-((double)d / 64.0) * 13.815510557964274);
    double sn, cs;
    sincos(ang, &sn, &cs);

    float* p = buf + (size_t)row * (nheads * 128) + h * 128 + d;
    float t1 = p[0];
    float t2 = p[64];
    p[0]  = t1 * (float)cs - t2 * (float)sn;
    p[64] = t2 * (float)cs + t1 * (float)sn;
}

// ---------------------------------------------------------------------------
// Flash attention (fp32, causal). BQ=64, BK=32, 256 threads.
// ---------------------------------------------------------------------------
__global__ __launch_bounds__(256)
void attn_kernel(const float* __restrict__ Q, const float* __restrict__ Kc,
                 const float* __restrict__ Vc, const int* __restrict__ sidx,
                 float* __restrict__ O)
{
    __shared__ float4 Ks[32][32];
    __shared__ float4 Vs[32][32];
    __shared__ int    spos[32];

    const int t   = threadIdx.x;
    const int r   = t >> 2;
    const int sub = t & 3;
    const int b   = blockIdx.z;
    const int h   = blockIdx.y;
    const int q0  = blockIdx.x * 64;
    const int kvh = h >> 2;
    const int sq  = q0 + r;
    const int pos_q = sidx[sq];
    const float scale = 0.08838834764831845f;

    float4 qreg[8];
    {
        const float4* qp = reinterpret_cast<const float4*>(
            Q + (size_t)(b * SEQ + sq) * QCOLS + h * 128 + sub * 32);
#pragma unroll
        for (int c = 0; c < 8; c++) qreg[c] = qp[c];
    }

    float  m = -1e30f, l = 0.f;
    float4 acc[8];
#pragma unroll
    for (int c = 0; c < 8; c++) acc[c] = make_float4(0.f, 0.f, 0.f, 0.f);

    const float* Kbase = Kc + (size_t)b * SEQ * KCOLS + kvh * 128;
    const float* Vbase = Vc + (size_t)b * SEQ * KCOLS + kvh * 128;

    for (int k0 = 0; k0 < q0 + 64; k0 += 32) {
        __syncthreads();
#pragma unroll
        for (int ww = 0; ww < 4; ww++) {
            int f  = ww * 256 + t;
            int j  = f >> 5;
            int i4 = f & 31;
            Ks[j][i4] = *reinterpret_cast<const float4*>(
                Kbase + (size_t)(k0 + j) * KCOLS + i4 * 4);
            Vs[j][i4] = *reinterpret_cast<const float4*>(
                Vbase + (size_t)(k0 + j) * KCOLS + i4 * 4);
        }
        if (t < 32) spos[t] = sidx[k0 + t];
        __syncthreads();

        float sc[32];
        float tmax = -1e30f;
#pragma unroll
        for (int j = 0; j < 32; j++) {
            float s = 0.f;
#pragma unroll
            for (int c0 = 0; c0 < 8; c0++) {
                int c = (c0 + 2 * sub) & 7;
                float4 k4 = Ks[j][sub * 8 + c];
                float4 q4 = qreg[c];
                s += q4.x * k4.x + q4.y * k4.y + q4.z * k4.z + q4.w * k4.w;
            }
            s += __shfl_xor_sync(0xffffffffu, s, 1);
            s += __shfl_xor_sync(0xffffffffu, s, 2);
            s *= scale;
            if (spos[j] > pos_q) s = -1e30f;
            sc[j] = s;
            tmax = fmaxf(tmax, s);
        }

        float m_new = fmaxf(m, tmax);
        float corr  = __expf(m - m_new);
        l *= corr;
#pragma unroll
        for (int c = 0; c < 8; c++) {
            acc[c].x *= corr; acc[c].y *= corr;
            acc[c].z *= corr; acc[c].w *= corr;
        }
#pragma unroll
        for (int j = 0; j < 32; j++) {
            float p = __expf(sc[j] - m_new);
            l += p;
#pragma unroll
            for (int c0 = 0; c0 < 8; c0++) {
                int c = (c0 + 2 * sub) & 7;
                float4 v4 = Vs[j][sub * 8 + c];
                acc[c].x += p * v4.x; acc[c].y += p * v4.y;
                acc[c].z += p * v4.z; acc[c].w += p * v4.w;
            }
        }
        m = m_new;
    }

    float inv = 1.0f / l;
    float4* op = reinterpret_cast<float4*>(
        O + (size_t)(b * SEQ + sq) * QCOLS + h * 128 + sub * 32);
#pragma unroll
    for (int c = 0; c < 8; c++) {
        float4 v = acc[c];
        v.x *= inv; v.y *= inv; v.z *= inv; v.w *= inv;
        op[c] = v;
    }
}

// ---------------------------------------------------------------------------
// Launch: QKV proj -> RoPE -> flash attention -> output proj
// ---------------------------------------------------------------------------
extern "C" void kernel_launch(void* const* d_in, const int* in_sizes, int n_in,
                              void* d_out, int out_size)
{
    (void)in_sizes; (void)n_in; (void)out_size;
    const float* x    = (const float*)d_in[0];
    const int*   sidx = (const int*)  d_in[1];
    const float* Wq = (const float*)d_in[4];
    const float* bq = (const float*)d_in[5];
    const float* Wk = (const float*)d_in[6];
    const float* bk = (const float*)d_in[7];
    const float* Wv = (const float*)d_in[8];
    const float* bv = (const float*)d_in[9];
    const float* Wo = (const float*)d_in[10];
    float* out = (float*)d_out;

    float *pQ, *pK, *pV, *pAO;
    cudaGetSymbolAddress((void**)&pQ,  g_Q);
    cudaGetSymbolAddress((void**)&pK,  g_K);
    cudaGetSymbolAddress((void**)&pV,  g_V);
    cudaGetSymbolAddress((void**)&pAO, g_AO);

    // QKV projections (+bias) — fp16 2-term split tensor-core GEMM
    gemm_f16s<<<dim3(QCOLS / 128, MROWS / 128), 256>>>(x, Wq, bq, pQ, MROWS, QCOLS, DMODEL);
    gemm_f16s<<<dim3(KCOLS / 128, MROWS / 128), 256>>>(x, Wk, bk, pK, MROWS, KCOLS, DMODEL);
    gemm_f16s<<<dim3(KCOLS / 128, MROWS / 128), 256>>>(x, Wv, bv, pV, MROWS, KCOLS, DMODEL);

    // RoPE on Q and K
    rope_kernel<<<(MROWS * NH   * 64 + 255) / 256, 256>>>(pQ, sidx, NH);
    rope_kernel<<<(MROWS * NKVH * 64 + 255) / 256, 256>>>(pK, sidx, NKVH);

    // Causal GQA flash attention
    attn_kernel<<<dim3(SEQ / 64, NH, BSZ), 256>>>(pQ, pK, pV, sidx, pAO);

    // Output projection
    gemm_f16s<<<dim3(DMODEL / 128, MROWS / 128), 256>>>(pAO, Wo, nullptr, out, MROWS, DMODEL, QCOLS);
}

// round 15
// speedup vs baseline: 1.2576x; 1.0048x over previous
#include <cuda_runtime.h>
#include <cuda_fp16.h>
#include <math.h>
#include <stdint.h>

// Problem constants
#define BSZ   2
#define SEQ   1024
#define DMODEL 4096
#define NH    32
#define NKVH  8
#define HD    128
#define MROWS (BSZ * SEQ)      // 2048
#define QCOLS (NH * HD)        // 4096
#define KCOLS (NKVH * HD)      // 1024

// Scratch (no allocations allowed — device globals)
__device__ float g_Q [(size_t)MROWS * QCOLS];
__device__ float g_K [(size_t)MROWS * KCOLS];
__device__ float g_V [(size_t)MROWS * KCOLS];
__device__ float g_AO[(size_t)MROWS * QCOLS];

// ---------------------------------------------------------------------------
// helpers
// ---------------------------------------------------------------------------
__device__ __forceinline__ uint32_t sptr(const void* p) {
    return (uint32_t)__cvta_generic_to_shared(p);
}
__device__ __forceinline__ void ldm4(uint32_t r[4], uint32_t addr) {
    asm volatile("ldmatrix.sync.aligned.m8n8.x4.shared.b16 {%0,%1,%2,%3}, [%4];"
                 : "=r"(r[0]), "=r"(r[1]), "=r"(r[2]), "=r"(r[3]) : "r"(addr));
}
__device__ __forceinline__ void ldm4t(uint32_t r[4], uint32_t addr) {
    asm volatile("ldmatrix.sync.aligned.m8n8.x4.trans.shared.b16 {%0,%1,%2,%3}, [%4];"
                 : "=r"(r[0]), "=r"(r[1]), "=r"(r[2]), "=r"(r[3]) : "r"(addr));
}
// fp16 mma: D(f32) += A(f16) * B(f16)
__device__ __forceinline__ void mma16816h(float c[4], const uint32_t a[4],
                                          uint32_t b0, uint32_t b1) {
    asm volatile("mma.sync.aligned.m16n8k16.row.col.f32.f16.f16.f32 "
                 "{%0,%1,%2,%3}, {%4,%5,%6,%7}, {%8,%9}, {%0,%1,%2,%3};"
                 : "+f"(c[0]), "+f"(c[1]), "+f"(c[2]), "+f"(c[3])
                 : "r"(a[0]), "r"(a[1]), "r"(a[2]), "r"(a[3]), "r"(b0), "r"(b1));
}

// fp32 pair -> packed f16x2 hi (RN) + lo (RN of residual). Low 16 bits = 'a'.
__device__ __forceinline__ void split2h(float a, float b, uint32_t& hi, uint32_t& lo) {
    __half2 h = __floats2half2_rn(a, b);
    hi = *reinterpret_cast<uint32_t*>(&h);
    float ha = __half2float(__low2half(h));
    float hb = __half2float(__high2half(h));
    __half2 l = __floats2half2_rn(a - ha, b - hb);
    lo = *reinterpret_cast<uint32_t*>(&l);
}
// fp32 pair -> packed f16x2 (RN). Low 16 bits = 'a'.
__device__ __forceinline__ uint32_t cvt2h(float a, float b) {
    __half2 h = __floats2half2_rn(a, b);
    return *reinterpret_cast<uint32_t*>(&h);
}

// ---------------------------------------------------------------------------
// fp16 2-term split tensor-core GEMM (16-warp, double-buffered):
//   C[M,N] = A[M,K] @ W[K,N] (+ bias[N]),  fp32 in/out.
//   A = Ah + Al (fp16 split); W fp16-quantized. C ≈ Ah@Bh + Al@Bh.
// CTA tile 128x128x32, 512 threads, 16 warps (4x4) of 32x32 warp tiles
// => 4 warps/SMSP for latency hiding.
// Dynamic smem, double-buffered, ONE __syncthreads per iteration.
// Per-buffer (shorts): Ah 128x40, Al 128x40, Bh 32x136 = 14592 shorts.
// ---------------------------------------------------------------------------
#define GBUF_SHORTS 14592
#define GEMM_SMEM   (2 * GBUF_SHORTS * 2)   // bytes = 58368

__global__ __launch_bounds__(512, 1)
void gemm_f16s(const float* __restrict__ A, const float* __restrict__ W,
               const float* __restrict__ bias, float* __restrict__ C,
               int M, int N, int K)
{
    extern __shared__ __align__(16) unsigned short sm[];

    const int t    = threadIdx.x;
    const int lane = t & 31;
    const int wid  = t >> 5;
    const int wm   = (wid & 3) * 32;     // warp row offset in CTA tile
    const int wn   = (wid >> 2) * 32;    // warp col offset
    const int row0 = blockIdx.y * 128;
    const int col0 = blockIdx.x * 128;

    float c[2][4][4];
#pragma unroll
    for (int i = 0; i < 2; i++)
#pragma unroll
        for (int j = 0; j < 4; j++)
#pragma unroll
            for (int e = 0; e < 4; e++) c[i][j][e] = 0.f;

    float4 pa[2], pb[2];

    auto LOAD = [&](int kb) {
#pragma unroll
        for (int q = 0; q < 2; q++) {
            int f = t + q * 512;                    // 0..1023
            pa[q] = *reinterpret_cast<const float4*>(
                A + (size_t)(row0 + (f >> 3)) * K + kb + (f & 7) * 4);
            pb[q] = *reinterpret_cast<const float4*>(
                W + (size_t)(kb + (f >> 5)) * N + col0 + (f & 31) * 4);
        }
    };
    auto STORE = [&](int buf) {
        unsigned short* Ah = sm + buf * GBUF_SHORTS;
        unsigned short* Al = Ah + 5120;
        unsigned short* Bh = Ah + 10240;
#pragma unroll
        for (int q = 0; q < 2; q++) {
            int f = t + q * 512;
            {   // A -> Ah/Al
                int r = f >> 3, ca = (f & 7) * 4;
                uint32_t h0, l0, h1, l1;
                split2h(pa[q].x, pa[q].y, h0, l0);
                split2h(pa[q].z, pa[q].w, h1, l1);
                *reinterpret_cast<uint32_t*>(Ah + r * 40 + ca)     = h0;
                *reinterpret_cast<uint32_t*>(Ah + r * 40 + ca + 2) = h1;
                *reinterpret_cast<uint32_t*>(Al + r * 40 + ca)     = l0;
                *reinterpret_cast<uint32_t*>(Al + r * 40 + ca + 2) = l1;
            }
            {   // B -> Bh
                int kk = f >> 5, cb = (f & 31) * 4;
                *reinterpret_cast<uint32_t*>(Bh + kk * 136 + cb)     = cvt2h(pb[q].x, pb[q].y);
                *reinterpret_cast<uint32_t*>(Bh + kk * 136 + cb + 2) = cvt2h(pb[q].z, pb[q].w);
            }
        }
    };

    LOAD(0);
    STORE(0);
    __syncthreads();

    const int lr = lane & 15;
    const int lc = (lane >> 4) << 3;

    const int niter = K >> 5;
    for (int it = 0; it < niter; it++) {
        const int cur = it & 1;
        if (it + 1 < niter) LOAD((it + 1) << 5);

        unsigned short* Ah = sm + cur * GBUF_SHORTS;
        unsigned short* Al = Ah + 5120;
        unsigned short* Bh = Ah + 10240;

#pragma unroll
        for (int ks = 0; ks < 2; ks++) {
            const int k0 = ks << 4;
            uint32_t ah[2][4], al4[2][4], bh[4][2];
#pragma unroll
            for (int mi = 0; mi < 2; mi++) {
                uint32_t off = (uint32_t)((wm + mi * 16 + lr) * 40 + k0 + lc);
                ldm4(ah[mi],  sptr(Ah + off));
                ldm4(al4[mi], sptr(Al + off));
            }
#pragma unroll
            for (int nh = 0; nh < 2; nh++) {
                uint32_t r4[4];
                ldm4t(r4, sptr(Bh + (uint32_t)((k0 + lr) * 136 + wn + nh * 16 + lc)));
                bh[nh * 2][0] = r4[0]; bh[nh * 2][1] = r4[1];
                bh[nh * 2 + 1][0] = r4[2]; bh[nh * 2 + 1][1] = r4[3];
            }
#pragma unroll
            for (int mi = 0; mi < 2; mi++)
#pragma unroll
                for (int ni = 0; ni < 4; ni++) {
                    mma16816h(c[mi][ni], ah[mi],  bh[ni][0], bh[ni][1]);
                    mma16816h(c[mi][ni], al4[mi], bh[ni][0], bh[ni][1]);
                }
        }

        if (it + 1 < niter) {
            STORE(cur ^ 1);
            __syncthreads();
        }
    }

    // Epilogue: m16n8 frag -> rows lane/4 (+8), cols (lane%4)*2
#pragma unroll
    for (int mi = 0; mi < 2; mi++)
#pragma unroll
        for (int ni = 0; ni < 4; ni++) {
            int r   = row0 + wm + mi * 16 + (lane >> 2);
            int col = col0 + wn + ni * 8 + (lane & 3) * 2;
            float bx = bias ? bias[col]     : 0.f;
            float by = bias ? bias[col + 1] : 0.f;
            float2 v0 = make_float2(c[mi][ni][0] + bx, c[mi][ni][1] + by);
            float2 v1 = make_float2(c[mi][ni][2] + bx, c[mi][ni][3] + by);
            *reinterpret_cast<float2*>(C + (size_t)r * N + col)       = v0;
            *reinterpret_cast<float2*>(C + (size_t)(r + 8) * N + col) = v1;
        }
}

// ---------------------------------------------------------------------------
// RoPE (in-place): buf layout [MROWS][nheads*128].
// ---------------------------------------------------------------------------
__global__ void rope_kernel(float* __restrict__ buf,
                            const int* __restrict__ sidx, int nheads)
{
    int idx = blockIdx.x * blockDim.x + threadIdx.x;
    int total = MROWS * nheads * 64;
    if (idx >= total) return;
    int d   = idx & 63;
    int rem = idx >> 6;
    int h   = rem % nheads;
    int row = rem / nheads;
    int s   = row & (SEQ - 1);

    double pos = (double)sidx[s];
    double ang = pos * exp(-((double)d / 64.0) * 13.815510557964274);
    double sn, cs;
    sincos(ang, &sn, &cs);

    float* p = buf + (size_t)row * (nheads * 128) + h * 128 + d;
    float t1 = p[0];
    float t2 = p[64];
    p[0]  = t1 * (float)cs - t2 * (float)sn;
    p[64] = t2 * (float)cs + t1 * (float)sn;
}

// ---------------------------------------------------------------------------
// Flash attention (fp32, causal). BQ=64, BK=32, 256 threads.
// ---------------------------------------------------------------------------
__global__ __launch_bounds__(256)
void attn_kernel(const float* __restrict__ Q, const float* __restrict__ Kc,
                 const float* __restrict__ Vc, const int* __restrict__ sidx,
                 float* __restrict__ O)
{
    __shared__ float4 Ks[32][32];
    __shared__ float4 Vs[32][32];
    __shared__ int    spos[32];

    const int t   = threadIdx.x;
    const int r   = t >> 2;
    const int sub = t & 3;
    const int b   = blockIdx.z;
    const int h   = blockIdx.y;
    const int q0  = blockIdx.x * 64;
    const int kvh = h >> 2;
    const int sq  = q0 + r;
    const int pos_q = sidx[sq];
    const float scale = 0.08838834764831845f;

    float4 qreg[8];
    {
        const float4* qp = reinterpret_cast<const float4*>(
            Q + (size_t)(b * SEQ + sq) * QCOLS + h * 128 + sub * 32);
#pragma unroll
        for (int c = 0; c < 8; c++) qreg[c] = qp[c];
    }

    float  m = -1e30f, l = 0.f;
    float4 acc[8];
#pragma unroll
    for (int c = 0; c < 8; c++) acc[c] = make_float4(0.f, 0.f, 0.f, 0.f);

    const float* Kbase = Kc + (size_t)b * SEQ * KCOLS + kvh * 128;
    const float* Vbase = Vc + (size_t)b * SEQ * KCOLS + kvh * 128;

    for (int k0 = 0; k0 < q0 + 64; k0 += 32) {
        __syncthreads();
#pragma unroll
        for (int ww = 0; ww < 4; ww++) {
            int f  = ww * 256 + t;
            int j  = f >> 5;
            int i4 = f & 31;
            Ks[j][i4] = *reinterpret_cast<const float4*>(
                Kbase + (size_t)(k0 + j) * KCOLS + i4 * 4);
            Vs[j][i4] = *reinterpret_cast<const float4*>(
                Vbase + (size_t)(k0 + j) * KCOLS + i4 * 4);
        }
        if (t < 32) spos[t] = sidx[k0 + t];
        __syncthreads();

        float sc[32];
        float tmax = -1e30f;
#pragma unroll
        for (int j = 0; j < 32; j++) {
            float s = 0.f;
#pragma unroll
            for (int c0 = 0; c0 < 8; c0++) {
                int c = (c0 + 2 * sub) & 7;
                float4 k4 = Ks[j][sub * 8 + c];
                float4 q4 = qreg[c];
                s += q4.x * k4.x + q4.y * k4.y + q4.z * k4.z + q4.w * k4.w;
            }
            s += __shfl_xor_sync(0xffffffffu, s, 1);
            s += __shfl_xor_sync(0xffffffffu, s, 2);
            s *= scale;
            if (spos[j] > pos_q) s = -1e30f;
            sc[j] = s;
            tmax = fmaxf(tmax, s);
        }

        float m_new = fmaxf(m, tmax);
        float corr  = __expf(m - m_new);
        l *= corr;
#pragma unroll
        for (int c = 0; c < 8; c++) {
            acc[c].x *= corr; acc[c].y *= corr;
            acc[c].z *= corr; acc[c].w *= corr;
        }
#pragma unroll
        for (int j = 0; j < 32; j++) {
            float p = __expf(sc[j] - m_new);
            l += p;
#pragma unroll
            for (int c0 = 0; c0 < 8; c0++) {
                int c = (c0 + 2 * sub) & 7;
                float4 v4 = Vs[j][sub * 8 + c];
                acc[c].x += p * v4.x; acc[c].y += p * v4.y;
                acc[c].z += p * v4.z; acc[c].w += p * v4.w;
            }
        }
        m = m_new;
    }

    float inv = 1.0f / l;
    float4* op = reinterpret_cast<float4*>(
        O + (size_t)(b * SEQ + sq) * QCOLS + h * 128 + sub * 32);
#pragma unroll
    for (int c = 0; c < 8; c++) {
        float4 v = acc[c];
        v.x *= inv; v.y *= inv; v.z *= inv; v.w *= inv;
        op[c] = v;
    }
}

// ---------------------------------------------------------------------------
// Launch: QKV proj -> RoPE -> flash attention -> output proj
// ---------------------------------------------------------------------------
extern "C" void kernel_launch(void* const* d_in, const int* in_sizes, int n_in,
                              void* d_out, int out_size)
{
    (void)in_sizes; (void)n_in; (void)out_size;
    const float* x    = (const float*)d_in[0];
    const int*   sidx = (const int*)  d_in[1];
    const float* Wq = (const float*)d_in[4];
    const float* bq = (const float*)d_in[5];
    const float* Wk = (const float*)d_in[6];
    const float* bk = (const float*)d_in[7];
    const float* Wv = (const float*)d_in[8];
    const float* bv = (const float*)d_in[9];
    const float* Wo = (const float*)d_in[10];
    float* out = (float*)d_out;

    float *pQ, *pK, *pV, *pAO;
    cudaGetSymbolAddress((void**)&pQ,  g_Q);
    cudaGetSymbolAddress((void**)&pK,  g_K);
    cudaGetSymbolAddress((void**)&pV,  g_V);
    cudaGetSymbolAddress((void**)&pAO, g_AO);

    cudaFuncSetAttribute(gemm_f16s, cudaFuncAttributeMaxDynamicSharedMemorySize, GEMM_SMEM);

    // QKV projections (+bias) — fp16 2-term split, 16-warp double-buffered
    gemm_f16s<<<dim3(QCOLS / 128, MROWS / 128), 512, GEMM_SMEM>>>(x, Wq, bq, pQ, MROWS, QCOLS, DMODEL);
    gemm_f16s<<<dim3(KCOLS / 128, MROWS / 128), 512, GEMM_SMEM>>>(x, Wk, bk, pK, MROWS, KCOLS, DMODEL);
    gemm_f16s<<<dim3(KCOLS / 128, MROWS / 128), 512, GEMM_SMEM>>>(x, Wv, bv, pV, MROWS, KCOLS, DMODEL);

    // RoPE on Q and K
    rope_kernel<<<(MROWS * NH   * 64 + 255) / 256, 256>>>(pQ, sidx, NH);
    rope_kernel<<<(MROWS * NKVH * 64 + 255) / 256, 256>>>(pK, sidx, NKVH);

    // Causal GQA flash attention
    attn_kernel<<<dim3(SEQ / 64, NH, BSZ), 256>>>(pQ, pK, pV, sidx, pAO);

    // Output projection
    gemm_f16s<<<dim3(DMODEL / 128, MROWS / 128), 512, GEMM_SMEM>>>(pAO, Wo, nullptr, out, MROWS, DMODEL, QCOLS);
}